// round 1
// baseline (speedup 1.0000x reference)
#include <cuda_runtime.h>

// MultiHeadAttention_41738492183140 — fp32 baseline (round 0)
// B=2, S=2048, E=1024, H=16, Dh=64 (hardcoded from setup_inputs)
//
// Stage 1: QKV = x @ w_qkv + b_qkv, scattered into Q/K/V [B,H,S,Dh]
// Stage 2: flash attention per (b,h): softmax(Q K^T * 0.125) V -> [B,S,E]
// Stage 3: out = attn_out @ w_proj + b_proj

#define BB 2
#define SS 2048
#define EE 1024
#define HH 16
#define DD 64
#define MTOT (BB*SS)   // 4096

// Scratch (allocation-free: __device__ globals)
__device__ float g_q[BB*HH*SS*DD];
__device__ float g_k[BB*HH*SS*DD];
__device__ float g_v[BB*HH*SS*DD];
__device__ float g_ao[BB*SS*EE];

// ---------------------------------------------------------------------------
// SGEMM: C[M,N] = A[M,K] @ B[K,N] + bias[N]
// 128x128 block tile, BK=8, 256 threads, 8x8 per thread, double-buffered smem.
// EPI==0: A = x (arg), output scattered to g_q/g_k/g_v  (N=3072)
// EPI==1: A = g_ao,    output written to C (d_out)       (N=1024)
// ---------------------------------------------------------------------------
template<int EPI>
__global__ __launch_bounds__(256) void sgemm_kernel(
    const float* __restrict__ A_in, const float* __restrict__ Bm,
    const float* __restrict__ bias, float* __restrict__ C,
    int M, int N, int K)
{
    __shared__ float As[2][8][128];   // [k][m] (transposed)
    __shared__ float Bs[2][8][128];   // [k][n]

    const float* A = (EPI == 1) ? g_ao : A_in;

    const int tid = threadIdx.x;
    const int bn = blockIdx.x, bm = blockIdx.y;
    const int tx = tid & 15, ty = tid >> 4;

    // A tile loader: 128 rows x 8 cols, float4 per thread
    const int a_row = tid >> 1;          // 0..127
    const int a_col = (tid & 1) * 4;     // 0 or 4
    // B tile loader: 8 rows x 128 cols, float4 per thread
    const int b_row = tid >> 5;          // 0..7
    const int b_col = (tid & 31) * 4;    // 0..124

    const float* Aptr = A  + (size_t)(bm*128 + a_row) * K + a_col;
    const float* Bptr = Bm + (size_t)b_row * N + bn*128 + b_col;

    float acc[8][8];
    #pragma unroll
    for (int i = 0; i < 8; i++)
        #pragma unroll
        for (int j = 0; j < 8; j++) acc[i][j] = 0.0f;

    // prologue: tile 0
    {
        float4 av = *(const float4*)Aptr;
        float4 bv = *(const float4*)Bptr;
        As[0][a_col+0][a_row] = av.x;
        As[0][a_col+1][a_row] = av.y;
        As[0][a_col+2][a_row] = av.z;
        As[0][a_col+3][a_row] = av.w;
        *(float4*)&Bs[0][b_row][b_col] = bv;
    }
    __syncthreads();

    const int KT = K >> 3;
    int buf = 0;
    for (int kt = 0; kt < KT; kt++) {
        float4 av2, bv2;
        const bool has_next = (kt + 1 < KT);
        if (has_next) {
            av2 = *(const float4*)(Aptr + (kt+1)*8);
            bv2 = *(const float4*)(Bptr + (size_t)(kt+1)*8*N);
        }
        #pragma unroll
        for (int k = 0; k < 8; k++) {
            float4 a0 = *(const float4*)&As[buf][k][ty*8];
            float4 a1 = *(const float4*)&As[buf][k][ty*8+4];
            float4 b0 = *(const float4*)&Bs[buf][k][tx*8];
            float4 b1 = *(const float4*)&Bs[buf][k][tx*8+4];
            float af[8] = {a0.x,a0.y,a0.z,a0.w,a1.x,a1.y,a1.z,a1.w};
            float bf[8] = {b0.x,b0.y,b0.z,b0.w,b1.x,b1.y,b1.z,b1.w};
            #pragma unroll
            for (int i = 0; i < 8; i++)
                #pragma unroll
                for (int j = 0; j < 8; j++)
                    acc[i][j] += af[i] * bf[j];
        }
        if (has_next) {
            const int nb = buf ^ 1;
            As[nb][a_col+0][a_row] = av2.x;
            As[nb][a_col+1][a_row] = av2.y;
            As[nb][a_col+2][a_row] = av2.z;
            As[nb][a_col+3][a_row] = av2.w;
            *(float4*)&Bs[nb][b_row][b_col] = bv2;
            __syncthreads();
            buf = nb;
        }
    }

    if (EPI == 0) {
        // scatter into Q/K/V [B,H,S,Dh]; n0 multiple of 8 -> 8 cols stay in one head
        const int n0 = bn*128 + tx*8;
        const int which = n0 >> 10;
        const int r = n0 & 1023;
        const int h = r >> 6, d = r & 63;
        float* dst = (which == 0) ? g_q : ((which == 1) ? g_k : g_v);
        float bi[8];
        #pragma unroll
        for (int j = 0; j < 8; j++) bi[j] = bias[n0 + j];
        #pragma unroll
        for (int i = 0; i < 8; i++) {
            const int m = bm*128 + ty*8 + i;
            const int b = m >> 11, s = m & 2047;
            float* p = dst + (((size_t)(b*HH + h) * SS + s) * DD + d);
            #pragma unroll
            for (int j = 0; j < 8; j++) p[j] = acc[i][j] + bi[j];
        }
    } else {
        const int n0 = bn*128 + tx*8;
        float bi[8];
        #pragma unroll
        for (int j = 0; j < 8; j++) bi[j] = bias[n0 + j];
        #pragma unroll
        for (int i = 0; i < 8; i++) {
            const int m = bm*128 + ty*8 + i;
            float* p = C + (size_t)m * N + n0;
            #pragma unroll
            for (int j = 0; j < 8; j++) p[j] = acc[i][j] + bi[j];
        }
    }
}

// ---------------------------------------------------------------------------
// Flash attention: one block = 64 query rows for one (b,h).
// 256 threads as 16(tx: key/d cols) x 16(ty: query rows), 4x4 per thread.
// Smem: Qs,Ks transposed [d][row] for float4 reads; Ks reused as P buffer.
// Static smem = 3 * 16KB = 48KB exactly.
// ---------------------------------------------------------------------------
__global__ __launch_bounds__(256) void attn_kernel()
{
    __shared__ float Qs[64][64];   // [d][m]
    __shared__ float Ks[64][64];   // [d][n]; later reused as Ps[m][n]
    __shared__ float Vs[64][64];   // [t][d]

    const int tid = threadIdx.x;
    const int tx = tid & 15, ty = tid >> 4;
    const int bh = blockIdx.y;               // b*16 + h
    const int q0 = blockIdx.x * 64;

    const float* Q = g_q + (size_t)bh * SS * DD;
    const float* K = g_k + (size_t)bh * SS * DD;
    const float* V = g_v + (size_t)bh * SS * DD;

    // load Q tile (transposed into Qs[d][m])
    {
        const int lr = tid >> 4;             // 0..15
        const int c4 = (tid & 15) * 4;       // 0..60
        #pragma unroll
        for (int it = 0; it < 4; it++) {
            const int row = it*16 + lr;
            float4 qv = *(const float4*)(Q + (size_t)(q0 + row)*DD + c4);
            Qs[c4+0][row] = qv.x; Qs[c4+1][row] = qv.y;
            Qs[c4+2][row] = qv.z; Qs[c4+3][row] = qv.w;
        }
    }

    float o[4][4];
    #pragma unroll
    for (int i = 0; i < 4; i++)
        #pragma unroll
        for (int j = 0; j < 4; j++) o[i][j] = 0.0f;
    float mrow[4] = {-1e30f, -1e30f, -1e30f, -1e30f};
    float lrow[4] = {0.0f, 0.0f, 0.0f, 0.0f};
    const float scale = 0.125f;   // 64^-0.5

    for (int t0 = 0; t0 < SS; t0 += 64) {
        __syncthreads();   // prior PV reads of Ks(P)/Vs done; Q stores visible (1st iter)
        // load K tile transposed, V tile natural
        {
            const int lr = tid >> 4;
            const int c4 = (tid & 15) * 4;
            #pragma unroll
            for (int it = 0; it < 4; it++) {
                const int row = it*16 + lr;
                float4 kv = *(const float4*)(K + (size_t)(t0 + row)*DD + c4);
                Ks[c4+0][row] = kv.x; Ks[c4+1][row] = kv.y;
                Ks[c4+2][row] = kv.z; Ks[c4+3][row] = kv.w;
                float4 vv = *(const float4*)(V + (size_t)(t0 + row)*DD + c4);
                *(float4*)&Vs[row][c4] = vv;
            }
        }
        __syncthreads();

        // S = Q K^T (4x4 per thread)
        float s[4][4];
        #pragma unroll
        for (int i = 0; i < 4; i++)
            #pragma unroll
            for (int j = 0; j < 4; j++) s[i][j] = 0.0f;
        #pragma unroll 16
        for (int d = 0; d < 64; d++) {
            float4 a = *(const float4*)&Qs[d][ty*4];
            float4 b = *(const float4*)&Ks[d][tx*4];
            float af[4] = {a.x, a.y, a.z, a.w};
            float bf[4] = {b.x, b.y, b.z, b.w};
            #pragma unroll
            for (int i = 0; i < 4; i++)
                #pragma unroll
                for (int j = 0; j < 4; j++)
                    s[i][j] += af[i] * bf[j];
        }

        // online softmax (row stats across the 16 tx threads, shuffle width 16)
        #pragma unroll
        for (int i = 0; i < 4; i++) {
            #pragma unroll
            for (int j = 0; j < 4; j++) s[i][j] *= scale;
            float rm = fmaxf(fmaxf(s[i][0], s[i][1]), fmaxf(s[i][2], s[i][3]));
            #pragma unroll
            for (int off = 8; off >= 1; off >>= 1)
                rm = fmaxf(rm, __shfl_xor_sync(0xffffffffu, rm, off));
            const float mnew = fmaxf(mrow[i], rm);
            const float corr = __expf(mrow[i] - mnew);
            mrow[i] = mnew;
            float rs = 0.0f;
            #pragma unroll
            for (int j = 0; j < 4; j++) {
                s[i][j] = __expf(s[i][j] - mnew);
                rs += s[i][j];
            }
            #pragma unroll
            for (int off = 8; off >= 1; off >>= 1)
                rs += __shfl_xor_sync(0xffffffffu, rs, off);
            lrow[i] = lrow[i] * corr + rs;
            #pragma unroll
            for (int j = 0; j < 4; j++) o[i][j] *= corr;
        }

        __syncthreads();   // everyone done reading Ks before it becomes P
        float* Ps = &Ks[0][0];  // Ps[m][n], 64x64
        #pragma unroll
        for (int i = 0; i < 4; i++)
            *(float4*)&Ps[(ty*4 + i)*64 + tx*4] =
                make_float4(s[i][0], s[i][1], s[i][2], s[i][3]);
        __syncthreads();

        // O += P V
        #pragma unroll 16
        for (int t = 0; t < 64; t++) {
            float4 bv = *(const float4*)&Vs[t][tx*4];
            float bf[4] = {bv.x, bv.y, bv.z, bv.w};
            float af[4];
            #pragma unroll
            for (int i = 0; i < 4; i++) af[i] = Ps[(ty*4 + i)*64 + t];
            #pragma unroll
            for (int i = 0; i < 4; i++)
                #pragma unroll
                for (int j = 0; j < 4; j++)
                    o[i][j] += af[i] * bf[j];
        }
    }

    // epilogue: normalize and write [B,S,E] with e = h*64 + d
    const int b = bh >> 4, h = bh & 15;
    #pragma unroll
    for (int i = 0; i < 4; i++) {
        const int srow = q0 + ty*4 + i;
        const float inv = 1.0f / lrow[i];
        float4 ov = make_float4(o[i][0]*inv, o[i][1]*inv, o[i][2]*inv, o[i][3]*inv);
        *(float4*)(g_ao + ((size_t)(b*SS + srow)*EE + h*64 + tx*4)) = ov;
    }
}

// ---------------------------------------------------------------------------
extern "C" void kernel_launch(void* const* d_in, const int* in_sizes, int n_in,
                              void* d_out, int out_size) {
    (void)in_sizes; (void)n_in; (void)out_size;
    const float* x      = (const float*)d_in[0];
    const float* w_qkv  = (const float*)d_in[1];
    const float* b_qkv  = (const float*)d_in[2];
    const float* w_proj = (const float*)d_in[3];
    const float* b_proj = (const float*)d_in[4];
    float* out = (float*)d_out;

    // Stage 1: QKV GEMM (4096 x 3072 x 1024)
    dim3 g1(3*EE/128, MTOT/128);   // 24 x 32
    sgemm_kernel<0><<<g1, 256>>>(x, w_qkv, b_qkv, nullptr, MTOT, 3*EE, EE);

    // Stage 2: attention (32 q-tiles x 32 (b,h))
    dim3 g2(SS/64, BB*HH);
    attn_kernel<<<g2, 256>>>();

    // Stage 3: proj GEMM (4096 x 1024 x 1024)
    dim3 g3(EE/128, MTOT/128);     // 8 x 32
    sgemm_kernel<1><<<g3, 256>>>(nullptr, w_proj, b_proj, out, MTOT, EE, EE);
}

// round 2
// speedup vs baseline: 2.7046x; 2.7046x over previous
#include <cuda_runtime.h>
#include <cstdint>

// MultiHeadAttention_41738492183140 — round 2: tf32 mma.sync everywhere
// B=2, S=2048, E=1024, H=16, Dh=64

#define BB 2
#define SS 2048
#define EE 1024
#define HH 16
#define DD 64
#define MTOT (BB*SS)   // 4096

__device__ float g_q[BB*HH*SS*DD];
__device__ float g_k[BB*HH*SS*DD];
__device__ float g_v[BB*HH*SS*DD];
__device__ float g_ao[BB*SS*EE];

__device__ __forceinline__ uint32_t f2tf(float f) {
    uint32_t u;
    asm("cvt.rna.tf32.f32 %0, %1;" : "=r"(u) : "f"(f));
    return u;
}

// D = A(16x8,row) @ B(8x8,col) + D, tf32 in, f32 accum
__device__ __forceinline__ void mma_tf32(float* c, const uint32_t* a, const uint32_t* b) {
    asm volatile(
        "mma.sync.aligned.m16n8k8.row.col.f32.tf32.tf32.f32 "
        "{%0,%1,%2,%3}, {%4,%5,%6,%7}, {%8,%9}, {%0,%1,%2,%3};\n"
        : "+f"(c[0]), "+f"(c[1]), "+f"(c[2]), "+f"(c[3])
        : "r"(a[0]), "r"(a[1]), "r"(a[2]), "r"(a[3]), "r"(b[0]), "r"(b[1]));
}

// ---------------------------------------------------------------------------
// tf32 GEMM: C[M,N] = A[M,K] @ B[K,N] + bias
// 128x128 tile, BK=16, 256 threads = 8 warps (2x4), warp tile 64x32.
// EPI==0: A = x, scatter to g_q/g_k/g_v.  EPI==1: A = g_ao, write C.
// ---------------------------------------------------------------------------
template<int EPI>
__global__ __launch_bounds__(256) void gemm_tf32_kernel(
    const float* __restrict__ A_in, const float* __restrict__ Bm,
    const float* __restrict__ bias, float* __restrict__ C,
    int M, int N, int K)
{
    __shared__ uint32_t As[2][128][20];   // [m][k], stride 20 -> conflict-free frags
    __shared__ uint32_t Bs[2][16][136];   // [k][n], stride 136 -> conflict-free frags

    const float* A = (EPI == 1) ? g_ao : A_in;

    const int tid  = threadIdx.x;
    const int warp = tid >> 5;
    const int lane = tid & 31;
    const int g    = lane >> 2;   // group (row within frag)
    const int tig  = lane & 3;    // thread-in-group (k / col pair)
    const int wm   = (warp >> 2) * 64;   // warp m offset (0,64)
    const int wn   = (warp & 3) * 32;    // warp n offset (0..96)
    const int bn = blockIdx.x, bm = blockIdx.y;

    // cooperative loaders
    const int a_row = tid >> 1;            // 0..127
    const int a_k   = (tid & 1) * 8;       // 0 or 8
    const int b_k   = tid >> 4;            // 0..15
    const int b_n   = (tid & 15) * 8;      // 0..120

    const float* Aptr = A  + (size_t)(bm * 128 + a_row) * K + a_k;
    const float* Bptr = Bm + (size_t)b_k * N + bn * 128 + b_n;

    float acc[4][4][4];
    #pragma unroll
    for (int mi = 0; mi < 4; mi++)
        #pragma unroll
        for (int ni = 0; ni < 4; ni++)
            #pragma unroll
            for (int r = 0; r < 4; r++) acc[mi][ni][r] = 0.0f;

    // prologue: tile 0 -> smem (cvt to tf32)
    {
        float4 av0 = *(const float4*)(Aptr);
        float4 av1 = *(const float4*)(Aptr + 4);
        float4 bv0 = *(const float4*)(Bptr);
        float4 bv1 = *(const float4*)(Bptr + 4);
        As[0][a_row][a_k+0] = f2tf(av0.x); As[0][a_row][a_k+1] = f2tf(av0.y);
        As[0][a_row][a_k+2] = f2tf(av0.z); As[0][a_row][a_k+3] = f2tf(av0.w);
        As[0][a_row][a_k+4] = f2tf(av1.x); As[0][a_row][a_k+5] = f2tf(av1.y);
        As[0][a_row][a_k+6] = f2tf(av1.z); As[0][a_row][a_k+7] = f2tf(av1.w);
        Bs[0][b_k][b_n+0] = f2tf(bv0.x); Bs[0][b_k][b_n+1] = f2tf(bv0.y);
        Bs[0][b_k][b_n+2] = f2tf(bv0.z); Bs[0][b_k][b_n+3] = f2tf(bv0.w);
        Bs[0][b_k][b_n+4] = f2tf(bv1.x); Bs[0][b_k][b_n+5] = f2tf(bv1.y);
        Bs[0][b_k][b_n+6] = f2tf(bv1.z); Bs[0][b_k][b_n+7] = f2tf(bv1.w);
    }
    __syncthreads();

    const int KT = K >> 4;   // BK=16
    int buf = 0;
    #pragma unroll 1
    for (int kt = 0; kt < KT; kt++) {
        float4 av0, av1, bv0, bv1;
        const bool has_next = (kt + 1 < KT);
        if (has_next) {
            av0 = *(const float4*)(Aptr + (kt+1)*16);
            av1 = *(const float4*)(Aptr + (kt+1)*16 + 4);
            bv0 = *(const float4*)(Bptr + (size_t)(kt+1)*16*N);
            bv1 = *(const float4*)(Bptr + (size_t)(kt+1)*16*N + 4);
        }
        #pragma unroll
        for (int ks = 0; ks < 2; ks++) {
            const int kb = ks * 8;
            uint32_t af[4][4];
            #pragma unroll
            for (int mi = 0; mi < 4; mi++) {
                const int r = wm + mi*16;
                af[mi][0] = As[buf][r + g    ][kb + tig    ];
                af[mi][1] = As[buf][r + g + 8][kb + tig    ];
                af[mi][2] = As[buf][r + g    ][kb + tig + 4];
                af[mi][3] = As[buf][r + g + 8][kb + tig + 4];
            }
            uint32_t bf[4][2];
            #pragma unroll
            for (int ni = 0; ni < 4; ni++) {
                const int c = wn + ni*8 + g;
                bf[ni][0] = Bs[buf][kb + tig    ][c];
                bf[ni][1] = Bs[buf][kb + tig + 4][c];
            }
            #pragma unroll
            for (int mi = 0; mi < 4; mi++)
                #pragma unroll
                for (int ni = 0; ni < 4; ni++)
                    mma_tf32(acc[mi][ni], af[mi], bf[ni]);
        }
        if (has_next) {
            const int nb = buf ^ 1;
            As[nb][a_row][a_k+0] = f2tf(av0.x); As[nb][a_row][a_k+1] = f2tf(av0.y);
            As[nb][a_row][a_k+2] = f2tf(av0.z); As[nb][a_row][a_k+3] = f2tf(av0.w);
            As[nb][a_row][a_k+4] = f2tf(av1.x); As[nb][a_row][a_k+5] = f2tf(av1.y);
            As[nb][a_row][a_k+6] = f2tf(av1.z); As[nb][a_row][a_k+7] = f2tf(av1.w);
            Bs[nb][b_k][b_n+0] = f2tf(bv0.x); Bs[nb][b_k][b_n+1] = f2tf(bv0.y);
            Bs[nb][b_k][b_n+2] = f2tf(bv0.z); Bs[nb][b_k][b_n+3] = f2tf(bv0.w);
            Bs[nb][b_k][b_n+4] = f2tf(bv1.x); Bs[nb][b_k][b_n+5] = f2tf(bv1.y);
            Bs[nb][b_k][b_n+6] = f2tf(bv1.z); Bs[nb][b_k][b_n+7] = f2tf(bv1.w);
            __syncthreads();
            buf = nb;
        }
    }

    // epilogue
    #pragma unroll
    for (int ni = 0; ni < 4; ni++) {
        const int n0 = bn*128 + wn + ni*8 + 2*tig;   // even col; pair (n0, n0+1)
        const float bi0 = bias[n0], bi1 = bias[n0 + 1];
        if (EPI == 0) {
            const int which = n0 >> 10;
            const int rr = n0 & 1023;
            const int h = rr >> 6, d = rr & 63;
            float* dst = (which == 0) ? g_q : ((which == 1) ? g_k : g_v);
            #pragma unroll
            for (int mi = 0; mi < 4; mi++) {
                #pragma unroll
                for (int hh2 = 0; hh2 < 2; hh2++) {
                    const int m = bm*128 + wm + mi*16 + g + hh2*8;
                    const int b = m >> 11, s = m & 2047;
                    float2 v = make_float2(acc[mi][ni][hh2*2+0] + bi0,
                                           acc[mi][ni][hh2*2+1] + bi1);
                    *(float2*)(dst + (((size_t)(b*HH + h) * SS + s) * DD + d)) = v;
                }
            }
        } else {
            #pragma unroll
            for (int mi = 0; mi < 4; mi++) {
                #pragma unroll
                for (int hh2 = 0; hh2 < 2; hh2++) {
                    const int m = bm*128 + wm + mi*16 + g + hh2*8;
                    float2 v = make_float2(acc[mi][ni][hh2*2+0] + bi0,
                                           acc[mi][ni][hh2*2+1] + bi1);
                    *(float2*)(C + (size_t)m * N + n0) = v;
                }
            }
        }
    }
}

// ---------------------------------------------------------------------------
// Flash attention, tf32 mma. Block = 64 queries x one (b,h); 4 warps (128 thr),
// warp w owns query rows [w*16, w*16+16). Key tile = 64.
// Q fragments live in registers. KPs buffer: K tile [n][k], reused as P [m][t].
// Vs: V transposed [d][t]. Stride 68 -> conflict-free fragment reads.
// ---------------------------------------------------------------------------
__global__ __launch_bounds__(128) void attn_kernel()
{
    __shared__ uint32_t KPs[64][68];
    __shared__ uint32_t Vs[64][68];

    const int tid  = threadIdx.x;
    const int warp = tid >> 5;
    const int lane = tid & 31;
    const int g    = lane >> 2;
    const int tig  = lane & 3;
    const int bh = blockIdx.y;
    const int q0 = blockIdx.x * 64;

    const float* Q = g_q + (size_t)bh * SS * DD;
    const float* K = g_k + (size_t)bh * SS * DD;
    const float* V = g_v + (size_t)bh * SS * DD;

    // Q fragments in registers: rows warp*16 + {g, g+8}, all 8 k-steps
    uint32_t qf[8][4];
    {
        const float* Qp = Q + (size_t)(q0 + warp*16) * DD;
        #pragma unroll
        for (int kk = 0; kk < 8; kk++) {
            qf[kk][0] = f2tf(Qp[(size_t)(g    ) * DD + kk*8 + tig    ]);
            qf[kk][1] = f2tf(Qp[(size_t)(g + 8) * DD + kk*8 + tig    ]);
            qf[kk][2] = f2tf(Qp[(size_t)(g    ) * DD + kk*8 + tig + 4]);
            qf[kk][3] = f2tf(Qp[(size_t)(g + 8) * DD + kk*8 + tig + 4]);
        }
    }

    float o[8][4];     // O: 8 d-tiles x (2 rows x 2 cols)
    #pragma unroll
    for (int ni = 0; ni < 8; ni++)
        #pragma unroll
        for (int r = 0; r < 4; r++) o[ni][r] = 0.0f;
    float m0 = -1e30f, m1 = -1e30f, l0 = 0.0f, l1 = 0.0f;
    const float scale = 0.125f;

    #pragma unroll 1
    for (int t0 = 0; t0 < SS; t0 += 64) {
        __syncthreads();   // prior iteration fully done with KPs / Vs
        // load K tile -> KPs[n][k]; V tile -> Vs[d][t] (transposed)
        {
            const int lr = tid >> 4;          // 0..7
            const int c4 = (tid & 15) * 4;    // 0..60
            #pragma unroll
            for (int it = 0; it < 8; it++) {
                const int row = it*8 + lr;
                float4 kv = *(const float4*)(K + (size_t)(t0 + row)*DD + c4);
                KPs[row][c4+0] = f2tf(kv.x); KPs[row][c4+1] = f2tf(kv.y);
                KPs[row][c4+2] = f2tf(kv.z); KPs[row][c4+3] = f2tf(kv.w);
                float4 vv = *(const float4*)(V + (size_t)(t0 + row)*DD + c4);
                Vs[c4+0][row] = f2tf(vv.x); Vs[c4+1][row] = f2tf(vv.y);
                Vs[c4+2][row] = f2tf(vv.z); Vs[c4+3][row] = f2tf(vv.w);
            }
        }
        __syncthreads();

        // S = Q K^T : 8 n-tiles of 8 keys
        float s[8][4];
        #pragma unroll
        for (int ni = 0; ni < 8; ni++)
            #pragma unroll
            for (int r = 0; r < 4; r++) s[ni][r] = 0.0f;
        #pragma unroll
        for (int kk = 0; kk < 8; kk++) {
            const int kb = kk * 8;
            #pragma unroll
            for (int ni = 0; ni < 8; ni++) {
                uint32_t bf[2];
                bf[0] = KPs[ni*8 + g][kb + tig    ];
                bf[1] = KPs[ni*8 + g][kb + tig + 4];
                mma_tf32(s[ni], qf[kk], bf);
            }
        }

        // online softmax: row0 = warp*16+g (regs 0,1), row1 = +8 (regs 2,3)
        float rm0 = -1e30f, rm1 = -1e30f;
        #pragma unroll
        for (int ni = 0; ni < 8; ni++) {
            s[ni][0] *= scale; s[ni][1] *= scale;
            s[ni][2] *= scale; s[ni][3] *= scale;
            rm0 = fmaxf(rm0, fmaxf(s[ni][0], s[ni][1]));
            rm1 = fmaxf(rm1, fmaxf(s[ni][2], s[ni][3]));
        }
        #pragma unroll
        for (int off = 1; off <= 2; off <<= 1) {
            rm0 = fmaxf(rm0, __shfl_xor_sync(0xffffffffu, rm0, off));
            rm1 = fmaxf(rm1, __shfl_xor_sync(0xffffffffu, rm1, off));
        }
        const float mn0 = fmaxf(m0, rm0), mn1 = fmaxf(m1, rm1);
        const float c0 = __expf(m0 - mn0), c1 = __expf(m1 - mn1);
        m0 = mn0; m1 = mn1;
        float rs0 = 0.0f, rs1 = 0.0f;
        #pragma unroll
        for (int ni = 0; ni < 8; ni++) {
            s[ni][0] = __expf(s[ni][0] - mn0); s[ni][1] = __expf(s[ni][1] - mn0);
            s[ni][2] = __expf(s[ni][2] - mn1); s[ni][3] = __expf(s[ni][3] - mn1);
            rs0 += s[ni][0] + s[ni][1];
            rs1 += s[ni][2] + s[ni][3];
        }
        #pragma unroll
        for (int off = 1; off <= 2; off <<= 1) {
            rs0 += __shfl_xor_sync(0xffffffffu, rs0, off);
            rs1 += __shfl_xor_sync(0xffffffffu, rs1, off);
        }
        l0 = l0 * c0 + rs0;
        l1 = l1 * c1 + rs1;
        #pragma unroll
        for (int ni = 0; ni < 8; ni++) {
            o[ni][0] *= c0; o[ni][1] *= c0;
            o[ni][2] *= c1; o[ni][3] *= c1;
        }

        __syncthreads();   // all warps done reading K before overwrite as P

        // write P (tf32) into KPs as [m][t]; warp-private rows
        {
            const int r0 = warp*16 + g, r1 = r0 + 8;
            #pragma unroll
            for (int ni = 0; ni < 8; ni++) {
                const int tcol = ni*8 + 2*tig;
                uint2 p0 = make_uint2(f2tf(s[ni][0]), f2tf(s[ni][1]));
                uint2 p1 = make_uint2(f2tf(s[ni][2]), f2tf(s[ni][3]));
                *(uint2*)&KPs[r0][tcol] = p0;
                *(uint2*)&KPs[r1][tcol] = p1;
            }
        }
        __syncwarp();

        // O += P V
        #pragma unroll
        for (int tk = 0; tk < 8; tk++) {
            const int tb = tk * 8;
            uint32_t af[4];
            af[0] = KPs[warp*16 + g    ][tb + tig    ];
            af[1] = KPs[warp*16 + g + 8][tb + tig    ];
            af[2] = KPs[warp*16 + g    ][tb + tig + 4];
            af[3] = KPs[warp*16 + g + 8][tb + tig + 4];
            #pragma unroll
            for (int ni = 0; ni < 8; ni++) {
                uint32_t bf[2];
                bf[0] = Vs[ni*8 + g][tb + tig    ];
                bf[1] = Vs[ni*8 + g][tb + tig + 4];
                mma_tf32(o[ni], af, bf);
            }
        }
    }

    // epilogue: write [B,S,E], e = h*64 + d
    const int b = bh >> 4, h = bh & 15;
    const float inv0 = 1.0f / l0, inv1 = 1.0f / l1;
    const int r0 = q0 + warp*16 + g, r1 = r0 + 8;
    #pragma unroll
    for (int ni = 0; ni < 8; ni++) {
        const int d = ni*8 + 2*tig;
        float2 v0 = make_float2(o[ni][0]*inv0, o[ni][1]*inv0);
        float2 v1 = make_float2(o[ni][2]*inv1, o[ni][3]*inv1);
        *(float2*)(g_ao + ((size_t)(b*SS + r0)*EE + h*64 + d)) = v0;
        *(float2*)(g_ao + ((size_t)(b*SS + r1)*EE + h*64 + d)) = v1;
    }
}

// ---------------------------------------------------------------------------
extern "C" void kernel_launch(void* const* d_in, const int* in_sizes, int n_in,
                              void* d_out, int out_size) {
    (void)in_sizes; (void)n_in; (void)out_size;
    const float* x      = (const float*)d_in[0];
    const float* w_qkv  = (const float*)d_in[1];
    const float* b_qkv  = (const float*)d_in[2];
    const float* w_proj = (const float*)d_in[3];
    const float* b_proj = (const float*)d_in[4];
    float* out = (float*)d_out;

    dim3 g1(3*EE/128, MTOT/128);   // 24 x 32
    gemm_tf32_kernel<0><<<g1, 256>>>(x, w_qkv, b_qkv, nullptr, MTOT, 3*EE, EE);

    dim3 g2(SS/64, BB*HH);         // 32 x 32
    attn_kernel<<<g2, 128>>>();

    dim3 g3(EE/128, MTOT/128);     // 8 x 32
    gemm_tf32_kernel<1><<<g3, 256>>>(nullptr, w_proj, b_proj, out, MTOT, EE, EE);
}